// round 2
// baseline (speedup 1.0000x reference)
#include <cuda_runtime.h>
#include <cuda_bf16.h>
#include <cstddef>

// Partial sums: combo = dir*T*B + t*B + b  (<= 12 combos), up to 64 x-blocks each.
#define MAX_COMBO 16
#define MAX_NBX   64
__device__ float g_nd2_part[MAX_COMBO * MAX_NBX];
__device__ float g_opp_part[MAX_COMBO * MAX_NBX];

// ---------------------------------------------------------------------------
// Brute-force nearest neighbor over the target cloud held in SMEM (xyz only,
// 24KB at N=2048). 128 threads/block, each thread handles 2 source points.
// For t==0 we also track argmin; partner flow is read from GLOBAL at the end
// (one lookup per source point), keeping smem under the 48KB default cap.
// ---------------------------------------------------------------------------
__global__ void __launch_bounds__(128) knn_kernel(
    const float* __restrict__ pc0, const float* __restrict__ pc1,
    const float* __restrict__ ffw, const float* __restrict__ fbw,
    int B, int N, int T)
{
    const int combo = blockIdx.y;
    const int b   = combo % B;
    const int t   = (combo / B) % T;
    const int dir = combo / (B * T);

    const float* src_pc = (dir == 0) ? pc0 : pc1;
    const float* tgt_pc = (dir == 0) ? pc1 : pc0;
    const float* src_fl = (dir == 0) ? ffw : fbw;
    const float* tgt_fl = (dir == 0) ? fbw : ffw;
    src_pc += (size_t)b * N * 3;
    tgt_pc += (size_t)b * N * 3;
    src_fl += ((size_t)t * B + b) * (size_t)N * 3;
    tgt_fl += ((size_t)t * B + b) * (size_t)N * 3;

    extern __shared__ float sm[];
    float* tx = sm;
    float* ty = sm + N;
    float* tz = sm + 2 * N;

    for (int i = threadIdx.x; i < N; i += blockDim.x) {
        tx[i] = tgt_pc[i * 3 + 0];
        ty[i] = tgt_pc[i * 3 + 1];
        tz[i] = tgt_pc[i * 3 + 2];
    }
    __syncthreads();

    const int n0 = blockIdx.x * 256 + (int)threadIdx.x;
    const int n1 = n0 + 128;
    const bool v0 = (n0 < N);
    const bool v1 = (n1 < N);

    float sfx0 = 0.f, sfy0 = 0.f, sfz0 = 0.f;
    float sfx1 = 0.f, sfy1 = 0.f, sfz1 = 0.f;
    float w0x = 0.f, w0y = 0.f, w0z = 0.f;
    float w1x = 0.f, w1y = 0.f, w1z = 0.f;
    if (v0) {
        sfx0 = src_fl[n0 * 3 + 0]; sfy0 = src_fl[n0 * 3 + 1]; sfz0 = src_fl[n0 * 3 + 2];
        w0x = src_pc[n0 * 3 + 0] + sfx0;
        w0y = src_pc[n0 * 3 + 1] + sfy0;
        w0z = src_pc[n0 * 3 + 2] + sfz0;
    }
    if (v1) {
        sfx1 = src_fl[n1 * 3 + 0]; sfy1 = src_fl[n1 * 3 + 1]; sfz1 = src_fl[n1 * 3 + 2];
        w1x = src_pc[n1 * 3 + 0] + sfx1;
        w1y = src_pc[n1 * 3 + 1] + sfy1;
        w1z = src_pc[n1 * 3 + 2] + sfz1;
    }

    float best0 = 3.402823466e+38f, best1 = 3.402823466e+38f;
    int   bi0 = 0, bi1 = 0;

    if (t == 0) {
        // argmin-tracking path (needed for opposite-flow partner lookup)
        #pragma unroll 4
        for (int j = 0; j < N; j++) {
            const float ax = tx[j], ay = ty[j], az = tz[j];
            float dx = w0x - ax, dy = w0y - ay, dz = w0z - az;
            float d2 = fmaf(dx, dx, fmaf(dy, dy, dz * dz));
            if (d2 < best0) { best0 = d2; bi0 = j; }
            dx = w1x - ax; dy = w1y - ay; dz = w1z - az;
            d2 = fmaf(dx, dx, fmaf(dy, dy, dz * dz));
            if (d2 < best1) { best1 = d2; bi1 = j; }
        }
    } else {
        // min-only path
        #pragma unroll 8
        for (int j = 0; j < N; j++) {
            const float ax = tx[j], ay = ty[j], az = tz[j];
            float dx = w0x - ax, dy = w0y - ay, dz = w0z - az;
            const float d20 = fmaf(dx, dx, fmaf(dy, dy, dz * dz));
            dx = w1x - ax; dy = w1y - ay; dz = w1z - az;
            const float d21 = fmaf(dx, dx, fmaf(dy, dy, dz * dz));
            best0 = fminf(best0, d20);
            best1 = fminf(best1, d21);
        }
    }

    float v_nd2 = 0.f, v_opp = 0.f;
    if (v0) v_nd2 += fmaxf(best0, 0.f);
    if (v1) v_nd2 += fmaxf(best1, 0.f);
    if (t == 0) {
        if (v0) {
            const float ox = sfx0 + tgt_fl[bi0 * 3 + 0];
            const float oy = sfy0 + tgt_fl[bi0 * 3 + 1];
            const float oz = sfz0 + tgt_fl[bi0 * 3 + 2];
            v_opp += fmaf(ox, ox, fmaf(oy, oy, oz * oz));
        }
        if (v1) {
            const float ox = sfx1 + tgt_fl[bi1 * 3 + 0];
            const float oy = sfy1 + tgt_fl[bi1 * 3 + 1];
            const float oz = sfz1 + tgt_fl[bi1 * 3 + 2];
            v_opp += fmaf(ox, ox, fmaf(oy, oy, oz * oz));
        }
    }

    // Deterministic block reduction (warp shuffle + smem across 4 warps).
    const int lane = threadIdx.x & 31;
    const int wid  = threadIdx.x >> 5;
    #pragma unroll
    for (int off = 16; off > 0; off >>= 1) {
        v_nd2 += __shfl_down_sync(0xffffffffu, v_nd2, off);
        v_opp += __shfl_down_sync(0xffffffffu, v_opp, off);
    }
    __shared__ float wnd[4], wop[4];
    if (lane == 0) { wnd[wid] = v_nd2; wop[wid] = v_opp; }
    __syncthreads();
    if (threadIdx.x == 0) {
        float snd = wnd[0] + wnd[1] + wnd[2] + wnd[3];
        float sop = wop[0] + wop[1] + wop[2] + wop[3];
        g_nd2_part[combo * gridDim.x + blockIdx.x] = snd;
        g_opp_part[combo * gridDim.x + blockIdx.x] = sop;
    }
}

// ---------------------------------------------------------------------------
// Single-block finisher: occlusion, static-flow, trafo-cycle losses +
// deterministic reduction of the KNN partials -> scalar total.
// ---------------------------------------------------------------------------
__global__ void __launch_bounds__(256) finish_kernel(
    const float* __restrict__ pc0, const float* __restrict__ pc1,
    const float* __restrict__ ffw, const float* __restrict__ fbw,
    const float* __restrict__ dfw, const float* __restrict__ dbw,
    const float* __restrict__ trfw, const float* __restrict__ trbw,
    const float* __restrict__ stfw, const float* __restrict__ stbw,
    float* __restrict__ out, int B, int N, int T, int nbx)
{
    const int BN = B * N;
    const int tid = threadIdx.x;

    float occ = 0.f, sffw = 0.f, sfbw = 0.f;
    for (int i = tid; i < BN; i += blockDim.x) {
        occ += dfw[i] + dbw[i];
        const int b = i / N;
        // forward static-flow residual
        {
            const float* tr = trfw + (size_t)b * 16;
            const float px = pc0[i * 3 + 0], py = pc0[i * 3 + 1], pz = pc0[i * 3 + 2];
            const float ix = tr[0] * px + tr[1] * py + tr[2]  * pz + tr[3]  - px;
            const float iy = tr[4] * px + tr[5] * py + tr[6]  * pz + tr[7]  - py;
            const float iz = tr[8] * px + tr[9] * py + tr[10] * pz + tr[11] - pz;
            const float* f = ffw + ((size_t)2 * BN + i) * 3;  // flows_fw[2]
            const float dx = f[0] - ix, dy = f[1] - iy, dz = f[2] - iz;
            sffw += stfw[i] * (dx * dx + dy * dy + dz * dz);
        }
        // backward static-flow residual
        {
            const float* tr = trbw + (size_t)b * 16;
            const float px = pc1[i * 3 + 0], py = pc1[i * 3 + 1], pz = pc1[i * 3 + 2];
            const float ix = tr[0] * px + tr[1] * py + tr[2]  * pz + tr[3]  - px;
            const float iy = tr[4] * px + tr[5] * py + tr[6]  * pz + tr[7]  - py;
            const float iz = tr[8] * px + tr[9] * py + tr[10] * pz + tr[11] - pz;
            const float* f = fbw + ((size_t)2 * BN + i) * 3;  // flows_bw[2]
            const float dx = f[0] - ix, dy = f[1] - iy, dz = f[2] - iz;
            sfbw += stbw[i] * (dx * dx + dy * dy + dz * dz);
        }
    }

    __shared__ float s0[256], s1[256], s2[256];
    s0[tid] = occ; s1[tid] = sffw; s2[tid] = sfbw;
    __syncthreads();
    for (int off = 128; off > 0; off >>= 1) {
        if (tid < off) {
            s0[tid] += s0[tid + off];
            s1[tid] += s1[tid + off];
            s2[tid] += s2[tid + off];
        }
        __syncthreads();
    }

    if (tid == 0) {
        // Reduce KNN partials (fixed order -> deterministic).
        float flow_s = 0.f, opp_s = 0.f, dyn_s = 0.f, stat_s = 0.f;
        for (int dir = 0; dir < 2; dir++) {
            for (int t = 0; t < T; t++) {
                for (int b = 0; b < B; b++) {
                    const int c = (dir * T + t) * B + b;
                    float s = 0.f, so = 0.f;
                    for (int x = 0; x < nbx; x++) {
                        s  += g_nd2_part[c * nbx + x];
                        so += g_opp_part[c * nbx + x];
                    }
                    if (t == 0)      { flow_s += s; opp_s += so; }
                    else if (t == 1) { dyn_s += s; }
                    else             { stat_s += s; }
                }
            }
        }
        const float inv = 1.0f / (float)BN;
        const float flow_loss = 0.5f * flow_s * inv;
        const float opp_loss  = 0.5f * opp_s  * inv;
        const float dyn_loss  = 0.5f * dyn_s  * inv;
        const float stat_loss = 0.5f * stat_s * inv;
        const float occl_loss = 0.5f * s0[0] * inv;
        const float sf_loss   = 0.5f * (s1[0] + s2[0]) * inv;

        // trafo cycle consistency: mean_b || T_fw[b] @ T_bw[b] - I ||_F^2
        float tl = 0.f;
        for (int b = 0; b < B; b++) {
            const float* A  = trfw + (size_t)b * 16;
            const float* Bm = trbw + (size_t)b * 16;
            for (int r = 0; r < 4; r++) {
                for (int k = 0; k < 4; k++) {
                    float c = 0.f;
                    for (int j = 0; j < 4; j++) c += A[r * 4 + j] * Bm[j * 4 + k];
                    const float d = c - ((r == k) ? 1.f : 0.f);
                    tl += d * d;
                }
            }
        }
        tl /= (float)B;

        // penalties: STATIC_FLOW=1, TRAFO=1, OCCL=0.1, KNN=1, DYN=0.5, STAT=0.5, OPP=1
        out[0] = 1.0f * sf_loss + 1.0f * tl + 0.1f * occl_loss
               + 1.0f * flow_loss + 0.5f * dyn_loss + 0.5f * stat_loss
               + 1.0f * opp_loss;
    }
}

extern "C" void kernel_launch(void* const* d_in, const int* in_sizes, int n_in,
                              void* d_out, int out_size)
{
    const float* pc0  = (const float*)d_in[0];
    const float* pc1  = (const float*)d_in[1];
    const float* ffw  = (const float*)d_in[2];
    const float* fbw  = (const float*)d_in[3];
    const float* dfw  = (const float*)d_in[4];
    const float* dbw  = (const float*)d_in[5];
    const float* trfw = (const float*)d_in[6];
    const float* trbw = (const float*)d_in[7];
    const float* stfw = (const float*)d_in[8];
    const float* stbw = (const float*)d_in[9];
    float* out = (float*)d_out;

    const int B = in_sizes[6] / 16;                 // trafo_fw = [B,4,4]
    const int N = in_sizes[0] / (3 * B);            // pc0 = [B,N,3]
    const int T = in_sizes[2] / (3 * B * N);        // flows_fw = [T,B,N,3]

    const int nbx = (N + 255) / 256;                // 256 source points per block
    dim3 grid(nbx, 2 * T * B);
    const size_t smem = (size_t)3 * N * sizeof(float);  // 24KB at N=2048

    knn_kernel<<<grid, 128, smem>>>(pc0, pc1, ffw, fbw, B, N, T);
    finish_kernel<<<1, 256>>>(pc0, pc1, ffw, fbw, dfw, dbw,
                              trfw, trbw, stfw, stbw, out, B, N, T, nbx);
}

// round 3
// speedup vs baseline: 1.2147x; 1.2147x over previous
#include <cuda_runtime.h>
#include <cuda_bf16.h>
#include <cstddef>

// Partials. combo = dir*T*B + t*B + b  (<=12), up to 64 x-blocks.
#define MAX_COMBO 16
#define MAX_NBX   64
__device__ float g_nd2_part[MAX_COMBO * MAX_NBX];
__device__ float g_opp_part[MAX_COMBO * MAX_NBX];
__device__ float g_occ_part[2 * MAX_NBX];
__device__ float g_sf_part [2 * MAX_NBX];

__device__ __forceinline__ void block_reduce2(float& a, float& b,
                                              float* sA, float* sB) {
    const int lane = threadIdx.x & 31;
    const int wid  = threadIdx.x >> 5;
    #pragma unroll
    for (int off = 16; off > 0; off >>= 1) {
        a += __shfl_down_sync(0xffffffffu, a, off);
        b += __shfl_down_sync(0xffffffffu, b, off);
    }
    if (lane == 0) { sA[wid] = a; sB[wid] = b; }
    __syncthreads();
    if (threadIdx.x == 0) {
        const int nw = (blockDim.x + 31) >> 5;
        float ra = 0.f, rb = 0.f;
        for (int w = 0; w < nw; w++) { ra += sA[w]; rb += sB[w]; }
        a = ra; b = rb;
    }
}

// ---------------------------------------------------------------------------
// Main kernel. blockIdx.y < 2*T*B: brute-force NN over the target cloud held
// in SMEM as float4 (x,y,z,|a|^2), using d2 = |a|^2 - 2 w.a + |w|^2 so the
// inner loop is 1 LDS.128 + 4 FP per point per target. Two source points per
// thread (ILP-2). blockIdx.y >= 2*T*B: occlusion + static-flow partials.
// ---------------------------------------------------------------------------
__global__ void __launch_bounds__(128) loss_kernel(
    const float* __restrict__ pc0, const float* __restrict__ pc1,
    const float* __restrict__ ffw, const float* __restrict__ fbw,
    const float* __restrict__ dfw, const float* __restrict__ dbw,
    const float* __restrict__ trfw, const float* __restrict__ trbw,
    const float* __restrict__ stfw, const float* __restrict__ stbw,
    int B, int N, int T)
{
    const int KC = 2 * T * B;
    const int combo = blockIdx.y;
    extern __shared__ float4 sm4[];
    __shared__ float sA[4], sB[4];

    if (combo < KC) {
        // ---------------- KNN path ----------------
        const int b   = combo % B;
        const int t   = (combo / B) % T;
        const int dir = combo / (B * T);

        const float* src_pc = (dir == 0) ? pc0 : pc1;
        const float* tgt_pc = (dir == 0) ? pc1 : pc0;
        const float* src_fl = (dir == 0) ? ffw : fbw;
        const float* tgt_fl = (dir == 0) ? fbw : ffw;
        src_pc += (size_t)b * N * 3;
        tgt_pc += (size_t)b * N * 3;
        src_fl += ((size_t)t * B + b) * (size_t)N * 3;
        tgt_fl += ((size_t)t * B + b) * (size_t)N * 3;

        for (int i = threadIdx.x; i < N; i += blockDim.x) {
            const float ax = tgt_pc[i * 3 + 0];
            const float ay = tgt_pc[i * 3 + 1];
            const float az = tgt_pc[i * 3 + 2];
            sm4[i] = make_float4(ax, ay, az, fmaf(ax, ax, fmaf(ay, ay, az * az)));
        }
        __syncthreads();

        const int n0 = blockIdx.x * 256 + (int)threadIdx.x;
        const int n1 = n0 + 128;
        const bool v0 = (n0 < N);
        const bool v1 = (n1 < N);

        float sfx0 = 0.f, sfy0 = 0.f, sfz0 = 0.f;
        float sfx1 = 0.f, sfy1 = 0.f, sfz1 = 0.f;
        float w0x = 0.f, w0y = 0.f, w0z = 0.f, w20 = 0.f;
        float w1x = 0.f, w1y = 0.f, w1z = 0.f, w21 = 0.f;
        if (v0) {
            sfx0 = src_fl[n0 * 3 + 0]; sfy0 = src_fl[n0 * 3 + 1]; sfz0 = src_fl[n0 * 3 + 2];
            w0x = src_pc[n0 * 3 + 0] + sfx0;
            w0y = src_pc[n0 * 3 + 1] + sfy0;
            w0z = src_pc[n0 * 3 + 2] + sfz0;
            w20 = fmaf(w0x, w0x, fmaf(w0y, w0y, w0z * w0z));
        }
        if (v1) {
            sfx1 = src_fl[n1 * 3 + 0]; sfy1 = src_fl[n1 * 3 + 1]; sfz1 = src_fl[n1 * 3 + 2];
            w1x = src_pc[n1 * 3 + 0] + sfx1;
            w1y = src_pc[n1 * 3 + 1] + sfy1;
            w1z = src_pc[n1 * 3 + 2] + sfz1;
            w21 = fmaf(w1x, w1x, fmaf(w1y, w1y, w1z * w1z));
        }

        float best0 = 3.402823466e+38f, best1 = 3.402823466e+38f;
        int   bi0 = 0, bi1 = 0;

        if (t == 0) {
            #pragma unroll 4
            for (int j = 0; j < N; j++) {
                const float4 a = sm4[j];
                float c0 = fmaf(a.x, w0x, fmaf(a.y, w0y, a.z * w0z));
                float s0 = fmaf(c0, -2.f, a.w);
                if (s0 < best0) { best0 = s0; bi0 = j; }
                float c1 = fmaf(a.x, w1x, fmaf(a.y, w1y, a.z * w1z));
                float s1 = fmaf(c1, -2.f, a.w);
                if (s1 < best1) { best1 = s1; bi1 = j; }
            }
        } else {
            #pragma unroll 8
            for (int j = 0; j < N; j++) {
                const float4 a = sm4[j];
                const float c0 = fmaf(a.x, w0x, fmaf(a.y, w0y, a.z * w0z));
                const float c1 = fmaf(a.x, w1x, fmaf(a.y, w1y, a.z * w1z));
                best0 = fminf(best0, fmaf(c0, -2.f, a.w));
                best1 = fminf(best1, fmaf(c1, -2.f, a.w));
            }
        }

        float v_nd2 = 0.f, v_opp = 0.f;
        if (v0) v_nd2 += fmaxf(best0 + w20, 0.f);
        if (v1) v_nd2 += fmaxf(best1 + w21, 0.f);
        if (t == 0) {
            if (v0) {
                const float ox = sfx0 + tgt_fl[bi0 * 3 + 0];
                const float oy = sfy0 + tgt_fl[bi0 * 3 + 1];
                const float oz = sfz0 + tgt_fl[bi0 * 3 + 2];
                v_opp += fmaf(ox, ox, fmaf(oy, oy, oz * oz));
            }
            if (v1) {
                const float ox = sfx1 + tgt_fl[bi1 * 3 + 0];
                const float oy = sfy1 + tgt_fl[bi1 * 3 + 1];
                const float oz = sfz1 + tgt_fl[bi1 * 3 + 2];
                v_opp += fmaf(ox, ox, fmaf(oy, oy, oz * oz));
            }
        }

        block_reduce2(v_nd2, v_opp, sA, sB);
        if (threadIdx.x == 0) {
            g_nd2_part[combo * gridDim.x + blockIdx.x] = v_nd2;
            g_opp_part[combo * gridDim.x + blockIdx.x] = v_opp;
        }
    } else {
        // ---------------- extras path: occlusion + static-flow ----------------
        const int dir = combo - KC;
        const float* pc  = (dir == 0) ? pc0  : pc1;
        const float* fl  = (dir == 0) ? ffw  : fbw;   // use slice [2]
        const float* dis = (dir == 0) ? dfw  : dbw;
        const float* st  = (dir == 0) ? stfw : stbw;
        const float* trg = (dir == 0) ? trfw : trbw;
        const int BN = B * N;
        fl += (size_t)2 * BN * 3;

        float occ = 0.f, sf = 0.f;
        for (int i = blockIdx.x * 128 + (int)threadIdx.x; i < BN;
             i += gridDim.x * 128) {
            occ += dis[i];
            const int b = i / N;
            const float* m = trg + (size_t)b * 16;
            const float px = pc[i * 3 + 0], py = pc[i * 3 + 1], pz = pc[i * 3 + 2];
            const float ix = fmaf(m[0], px, fmaf(m[1],  py, fmaf(m[2],  pz, m[3])))  - px;
            const float iy = fmaf(m[4], px, fmaf(m[5],  py, fmaf(m[6],  pz, m[7])))  - py;
            const float iz = fmaf(m[8], px, fmaf(m[9],  py, fmaf(m[10], pz, m[11]))) - pz;
            const float* f = fl + (size_t)i * 3;
            const float dx = f[0] - ix, dy = f[1] - iy, dz = f[2] - iz;
            sf += st[i] * fmaf(dx, dx, fmaf(dy, dy, dz * dz));
        }
        block_reduce2(occ, sf, sA, sB);
        if (threadIdx.x == 0) {
            g_occ_part[dir * gridDim.x + blockIdx.x] = occ;
            g_sf_part [dir * gridDim.x + blockIdx.x] = sf;
        }
    }
}

// ---------------------------------------------------------------------------
// Tiny fully parallel finisher: weighted reduction of all partials + trafo
// cycle loss (one thread per matrix entry) -> scalar total.
// ---------------------------------------------------------------------------
__global__ void __launch_bounds__(256) finish_kernel(
    const float* __restrict__ trfw, const float* __restrict__ trbw,
    float* __restrict__ out, int B, int N, int T, int nbx)
{
    const int KC = 2 * T * B;
    const int BN = B * N;
    const int tid = threadIdx.x;

    // accA collects everything divided by BN; accB the trafo loss (/B).
    float accA = 0.f, accB = 0.f;

    for (int i = tid; i < KC * nbx; i += blockDim.x) {
        const int c = i / nbx;
        const int t = (c / B) % T;
        // knn pen: t0 flow 1.0, t1 dyn 0.5, t2 stat 0.5 ; all * 0.5 (fw/bw avg)
        const float wnd = (t == 0) ? 0.5f : 0.25f;
        float v = wnd * g_nd2_part[i];
        if (t == 0) v += 0.5f * g_opp_part[i];   // opp pen 1.0 * 0.5
        accA += v;
    }
    for (int i = tid; i < 2 * nbx; i += blockDim.x) {
        // occl pen 0.1 * 0.5 ; static-flow pen 1.0 * 0.5
        accA += 0.05f * g_occ_part[i] + 0.5f * g_sf_part[i];
    }
    // trafo cycle: one thread per output entry (b, r, k)
    for (int e = tid; e < B * 16; e += blockDim.x) {
        const int b = e >> 4;
        const int r = (e >> 2) & 3;
        const int k = e & 3;
        const float* A  = trfw + (size_t)b * 16;
        const float* Bm = trbw + (size_t)b * 16;
        float c = 0.f;
        #pragma unroll
        for (int j = 0; j < 4; j++) c = fmaf(A[r * 4 + j], Bm[j * 4 + k], c);
        const float d = c - ((r == k) ? 1.f : 0.f);
        accB += d * d;
    }

    const int lane = tid & 31;
    const int wid  = tid >> 5;
    #pragma unroll
    for (int off = 16; off > 0; off >>= 1) {
        accA += __shfl_down_sync(0xffffffffu, accA, off);
        accB += __shfl_down_sync(0xffffffffu, accB, off);
    }
    __shared__ float sA[8], sB[8];
    if (lane == 0) { sA[wid] = accA; sB[wid] = accB; }
    __syncthreads();
    if (tid == 0) {
        float ra = 0.f, rb = 0.f;
        for (int w = 0; w < 8; w++) { ra += sA[w]; rb += sB[w]; }
        out[0] = ra / (float)BN + rb / (float)B;
    }
}

extern "C" void kernel_launch(void* const* d_in, const int* in_sizes, int n_in,
                              void* d_out, int out_size)
{
    const float* pc0  = (const float*)d_in[0];
    const float* pc1  = (const float*)d_in[1];
    const float* ffw  = (const float*)d_in[2];
    const float* fbw  = (const float*)d_in[3];
    const float* dfw  = (const float*)d_in[4];
    const float* dbw  = (const float*)d_in[5];
    const float* trfw = (const float*)d_in[6];
    const float* trbw = (const float*)d_in[7];
    const float* stfw = (const float*)d_in[8];
    const float* stbw = (const float*)d_in[9];
    float* out = (float*)d_out;

    const int B = in_sizes[6] / 16;                 // trafo_fw = [B,4,4]
    const int N = in_sizes[0] / (3 * B);            // pc0 = [B,N,3]
    const int T = in_sizes[2] / (3 * B * N);        // flows_fw = [T,B,N,3]

    const int nbx = (N + 255) / 256;                // 256 source points / block
    dim3 grid(nbx, 2 * T * B + 2);                  // +2 extras combos
    const size_t smem = (size_t)N * sizeof(float4); // 32KB at N=2048

    loss_kernel<<<grid, 128, smem>>>(pc0, pc1, ffw, fbw, dfw, dbw,
                                     trfw, trbw, stfw, stbw, B, N, T);
    finish_kernel<<<1, 256>>>(trfw, trbw, out, B, N, T, nbx);
}

// round 5
// speedup vs baseline: 2.5112x; 2.0673x over previous
#include <cuda_runtime.h>
#include <cuda_bf16.h>
#include <cstddef>

#define MAXC   16     // max combos (dir*T*B <= 12 here)
#define JSPLIT 4      // target-dimension split
#define MAXN   4096   // max points
#define MAXP   32     // max partial blocks per row

__device__ float g_best[MAXC * JSPLIT * MAXN];   // per-chunk min d2 (w2 included)
__device__ int   g_bidx[MAXC * JSPLIT * MAXN];   // per-chunk argmin (abs target idx)
__device__ float g_nd2_part[MAXC * MAXP];
__device__ float g_opp_part[MAXC * MAXP];
__device__ float g_occ_part[2 * MAXP];
__device__ float g_sf_part [2 * MAXP];
__device__ unsigned int g_ctr;                   // zero-init; wraps each launch

__device__ __forceinline__ void block_reduce2(float& a, float& b,
                                              float* sA, float* sB) {
    const int lane = threadIdx.x & 31;
    const int wid  = threadIdx.x >> 5;
    #pragma unroll
    for (int off = 16; off > 0; off >>= 1) {
        a += __shfl_down_sync(0xffffffffu, a, off);
        b += __shfl_down_sync(0xffffffffu, b, off);
    }
    if (lane == 0) { sA[wid] = a; sB[wid] = b; }
    __syncthreads();
    if (threadIdx.x == 0) {
        const int nw = (blockDim.x + 31) >> 5;
        float ra = 0.f, rb = 0.f;
        for (int w = 0; w < nw; w++) { ra += sA[w]; rb += sB[w]; }
        a = ra; b = rb;
    }
}

// ---------------------------------------------------------------------------
// Pass 1: per-(combo, point-block, target-chunk) partial NN.
// 256 threads, 2 source points/thread (512 pts/block), chunk of N/JSPLIT
// targets staged in SMEM as float4 (x,y,z,|a|^2). d2 = |a|^2 - 2 w.a + |w|^2.
// Extras rows (blockIdx.y >= KC): occlusion + static-flow partial sums.
// ---------------------------------------------------------------------------
__global__ void __launch_bounds__(256) chunk_kernel(
    const float* __restrict__ pc0, const float* __restrict__ pc1,
    const float* __restrict__ ffw, const float* __restrict__ fbw,
    const float* __restrict__ dfw, const float* __restrict__ dbw,
    const float* __restrict__ trfw, const float* __restrict__ trbw,
    const float* __restrict__ stfw, const float* __restrict__ stbw,
    int B, int N, int T)
{
    const int KC = 2 * T * B;
    const int combo = blockIdx.y;
    extern __shared__ float4 sm4[];
    __shared__ float sA[8], sB[8];

    if (combo < KC) {
        const int b   = combo % B;
        const int t   = (combo / B) % T;
        const int dir = combo / (B * T);
        const int chunk = (N + JSPLIT - 1) / JSPLIT;
        const int xb = blockIdx.x / JSPLIT;
        const int jc = blockIdx.x % JSPLIT;
        const int j0 = jc * chunk;
        const int cnt = min(chunk, N - j0);
        if (cnt <= 0) return;

        const float* src_pc = (dir == 0) ? pc0 : pc1;
        const float* tgt_pc = (dir == 0) ? pc1 : pc0;
        const float* src_fl = (dir == 0) ? ffw : fbw;
        src_pc += (size_t)b * N * 3;
        tgt_pc += (size_t)b * N * 3;
        src_fl += ((size_t)t * B + b) * (size_t)N * 3;

        for (int i = threadIdx.x; i < cnt; i += 256) {
            const float ax = tgt_pc[(j0 + i) * 3 + 0];
            const float ay = tgt_pc[(j0 + i) * 3 + 1];
            const float az = tgt_pc[(j0 + i) * 3 + 2];
            sm4[i] = make_float4(ax, ay, az, fmaf(ax, ax, fmaf(ay, ay, az * az)));
        }
        __syncthreads();

        const int n0 = xb * 512 + (int)threadIdx.x;
        const int n1 = n0 + 256;
        const bool v0 = (n0 < N);
        const bool v1 = (n1 < N);

        float w0x = 0.f, w0y = 0.f, w0z = 0.f, w20 = 0.f;
        float w1x = 0.f, w1y = 0.f, w1z = 0.f, w21 = 0.f;
        if (v0) {
            w0x = src_pc[n0 * 3 + 0] + src_fl[n0 * 3 + 0];
            w0y = src_pc[n0 * 3 + 1] + src_fl[n0 * 3 + 1];
            w0z = src_pc[n0 * 3 + 2] + src_fl[n0 * 3 + 2];
            w20 = fmaf(w0x, w0x, fmaf(w0y, w0y, w0z * w0z));
        }
        if (v1) {
            w1x = src_pc[n1 * 3 + 0] + src_fl[n1 * 3 + 0];
            w1y = src_pc[n1 * 3 + 1] + src_fl[n1 * 3 + 1];
            w1z = src_pc[n1 * 3 + 2] + src_fl[n1 * 3 + 2];
            w21 = fmaf(w1x, w1x, fmaf(w1y, w1y, w1z * w1z));
        }

        float best0 = 3.402823466e+38f, best1 = 3.402823466e+38f;
        int   bi0 = 0, bi1 = 0;

        if (t == 0) {
            #pragma unroll 4
            for (int j = 0; j < cnt; j++) {
                const float4 a = sm4[j];
                const float s0 = fmaf(fmaf(a.x, w0x, fmaf(a.y, w0y, a.z * w0z)), -2.f, a.w);
                if (s0 < best0) { best0 = s0; bi0 = j; }
                const float s1 = fmaf(fmaf(a.x, w1x, fmaf(a.y, w1y, a.z * w1z)), -2.f, a.w);
                if (s1 < best1) { best1 = s1; bi1 = j; }
            }
        } else {
            #pragma unroll 8
            for (int j = 0; j < cnt; j++) {
                const float4 a = sm4[j];
                const float c0 = fmaf(a.x, w0x, fmaf(a.y, w0y, a.z * w0z));
                const float c1 = fmaf(a.x, w1x, fmaf(a.y, w1y, a.z * w1z));
                best0 = fminf(best0, fmaf(c0, -2.f, a.w));
                best1 = fminf(best1, fmaf(c1, -2.f, a.w));
            }
        }

        float* bb = g_best + ((size_t)combo * JSPLIT + jc) * N;
        int*   ii = g_bidx + ((size_t)combo * JSPLIT + jc) * N;
        if (v0) { bb[n0] = best0 + w20; if (t == 0) ii[n0] = j0 + bi0; }
        if (v1) { bb[n1] = best1 + w21; if (t == 0) ii[n1] = j0 + bi1; }
    } else {
        // extras: occlusion + static-flow partials
        const int dir = combo - KC;
        const float* pc  = (dir == 0) ? pc0  : pc1;
        const float* fl  = (dir == 0) ? ffw  : fbw;
        const float* dis = (dir == 0) ? dfw  : dbw;
        const float* st  = (dir == 0) ? stfw : stbw;
        const float* trg = (dir == 0) ? trfw : trbw;
        const int BN = B * N;
        fl += (size_t)2 * BN * 3;

        float occ = 0.f, sf = 0.f;
        for (int i = blockIdx.x * 256 + (int)threadIdx.x; i < BN;
             i += gridDim.x * 256) {
            occ += dis[i];
            const int b = i / N;
            const float* m = trg + (size_t)b * 16;
            const float px = pc[i * 3 + 0], py = pc[i * 3 + 1], pz = pc[i * 3 + 2];
            const float ix = fmaf(m[0], px, fmaf(m[1],  py, fmaf(m[2],  pz, m[3])))  - px;
            const float iy = fmaf(m[4], px, fmaf(m[5],  py, fmaf(m[6],  pz, m[7])))  - py;
            const float iz = fmaf(m[8], px, fmaf(m[9],  py, fmaf(m[10], pz, m[11]))) - pz;
            const float* f = fl + (size_t)i * 3;
            const float dx = f[0] - ix, dy = f[1] - iy, dz = f[2] - iz;
            sf += st[i] * fmaf(dx, dx, fmaf(dy, dy, dz * dz));
        }
        block_reduce2(occ, sf, sA, sB);
        if (threadIdx.x == 0) {
            g_occ_part[dir * gridDim.x + blockIdx.x] = occ;
            g_sf_part [dir * gridDim.x + blockIdx.x] = sf;
        }
    }
}

// ---------------------------------------------------------------------------
// Pass 2: combine chunk partials (min over JSPLIT, first-occurrence ties),
// compute nd2 / opp sums; last block folds everything + trafo loss -> out.
// ---------------------------------------------------------------------------
__global__ void __launch_bounds__(256) combine_kernel(
    const float* __restrict__ ffw, const float* __restrict__ fbw,
    const float* __restrict__ trfw, const float* __restrict__ trbw,
    float* __restrict__ out, int B, int N, int T, int nbx1)
{
    const int combo = blockIdx.y;
    const int b   = combo % B;
    const int t   = (combo / B) % T;
    const int dir = combo / (B * T);
    const int KC  = 2 * T * B;
    const int tid = threadIdx.x;
    __shared__ float sA[8], sB[8];
    __shared__ bool isLast;

    const int n = blockIdx.x * 256 + tid;
    float v_nd2 = 0.f, v_opp = 0.f;
    if (n < N) {
        const float* bb = g_best + (size_t)combo * JSPLIT * N;
        float best = bb[n];
        int   jcb  = 0;
        #pragma unroll
        for (int jc = 1; jc < JSPLIT; jc++) {
            const float v = bb[(size_t)jc * N + n];
            if (v < best) { best = v; jcb = jc; }
        }
        v_nd2 = fmaxf(best, 0.f);
        if (t == 0) {
            const int idx = g_bidx[((size_t)combo * JSPLIT + jcb) * N + n];
            const float* src_fl = ((dir == 0) ? ffw : fbw) + ((size_t)t * B + b) * (size_t)N * 3;
            const float* tgt_fl = ((dir == 0) ? fbw : ffw) + ((size_t)t * B + b) * (size_t)N * 3;
            const float ox = src_fl[n * 3 + 0] + tgt_fl[idx * 3 + 0];
            const float oy = src_fl[n * 3 + 1] + tgt_fl[idx * 3 + 1];
            const float oz = src_fl[n * 3 + 2] + tgt_fl[idx * 3 + 2];
            v_opp = fmaf(ox, ox, fmaf(oy, oy, oz * oz));
        }
    }

    block_reduce2(v_nd2, v_opp, sA, sB);
    if (tid == 0) {
        g_nd2_part[combo * gridDim.x + blockIdx.x] = v_nd2;
        g_opp_part[combo * gridDim.x + blockIdx.x] = v_opp;
        __threadfence();
        const unsigned total = gridDim.x * gridDim.y;
        const unsigned old = atomicInc(&g_ctr, total - 1);   // wraps -> replay-safe
        isLast = (old == total - 1);
    }
    __syncthreads();
    if (!isLast) return;

    // ---- final reduction (one block, 256 threads) ----
    const int BN = B * N;
    const int nbxc = gridDim.x;
    float accA = 0.f, accB = 0.f;
    for (int i = tid; i < KC * nbxc; i += 256) {
        const int c  = i / nbxc;
        const int tt = (c / B) % T;
        const float wnd = (tt == 0) ? 0.5f : 0.25f;   // knn pens * 0.5 fw/bw
        float v = wnd * g_nd2_part[i];
        if (tt == 0) v += 0.5f * g_opp_part[i];
        accA += v;
    }
    for (int i = tid; i < 2 * nbx1; i += 256) {
        accA += 0.05f * g_occ_part[i] + 0.5f * g_sf_part[i];
    }
    for (int e = tid; e < B * 16; e += 256) {
        const int bb = e >> 4, r = (e >> 2) & 3, k = e & 3;
        const float* A  = trfw + (size_t)bb * 16;
        const float* Bm = trbw + (size_t)bb * 16;
        float c = 0.f;
        #pragma unroll
        for (int j = 0; j < 4; j++) c = fmaf(A[r * 4 + j], Bm[j * 4 + k], c);
        const float d = c - ((r == k) ? 1.f : 0.f);
        accB += d * d;
    }
    __syncthreads();
    block_reduce2(accA, accB, sA, sB);
    if (tid == 0) out[0] = accA / (float)BN + accB / (float)B;
}

extern "C" void kernel_launch(void* const* d_in, const int* in_sizes, int n_in,
                              void* d_out, int out_size)
{
    const float* pc0  = (const float*)d_in[0];
    const float* pc1  = (const float*)d_in[1];
    const float* ffw  = (const float*)d_in[2];
    const float* fbw  = (const float*)d_in[3];
    const float* dfw  = (const float*)d_in[4];
    const float* dbw  = (const float*)d_in[5];
    const float* trfw = (const float*)d_in[6];
    const float* trbw = (const float*)d_in[7];
    const float* stfw = (const float*)d_in[8];
    const float* stbw = (const float*)d_in[9];
    float* out = (float*)d_out;

    const int B = in_sizes[6] / 16;                 // trafo_fw = [B,4,4]
    const int N = in_sizes[0] / (3 * B);            // pc0 = [B,N,3]
    const int T = in_sizes[2] / (3 * B * N);        // flows_fw = [T,B,N,3]

    const int KC  = 2 * T * B;
    const int nbx = (N + 511) / 512;                // 512 source points / block
    const int chunk = (N + JSPLIT - 1) / JSPLIT;

    dim3 grid1(nbx * JSPLIT, KC + 2);
    const size_t smem = (size_t)chunk * sizeof(float4);   // 8KB at N=2048
    chunk_kernel<<<grid1, 256, smem>>>(pc0, pc1, ffw, fbw, dfw, dbw,
                                       trfw, trbw, stfw, stbw, B, N, T);

    dim3 grid2((N + 255) / 256, KC);
    combine_kernel<<<grid2, 256>>>(ffw, fbw, trfw, trbw, out,
                                   B, N, T, nbx * JSPLIT);
}